// round 9
// baseline (speedup 1.0000x reference)
#include <cuda_runtime.h>
#include <math.h>
#include <stdint.h>

// Biquad lowpass (fs=44100, fc=10000, Q=0.707) as truncated-FIR (K=12,
// pole mag 0.4203 -> trunc err ~3.8e-5 << 1e-3).
// R9: warp-private cp.async pipelines. Each warp owns a 4-stage ring of
// 144-float smem buffers and walks 18 tiles of 128 outputs on its own strip.
// cp.async groups are per-thread, and only the issuing warp consumes the
// data, so wait_group + __syncwarp suffices — ZERO block barriers.
// Buffer reuse needs no fence: warp-sequential order guarantees tile i-1 was
// consumed before stage (i+3)&3 is refilled.

#define K_TAPS   12
#define T_LEN    160000
#define WARPS    8
#define THREADS  (WARPS * 32)
#define WTILE    128                     // outputs per warp-tile
#define WHALO    16
#define WBUF_F   (WTILE + WHALO)         // 144 floats
#define WBUF_V4  (WBUF_F / 4)            // 36 float4
#define STAGES   4
#define NTW      18                      // tiles per warp
#define WSPAN    (WTILE * NTW)           // 2304 samples per warp strip
#define SPB      (WSPAN * WARPS)         // 18432 per block
#define BLOCKS_X 9                       // 9*18432 = 165888 >= 160000

struct FirParams {
    float h[K_TAPS];
};

__device__ __forceinline__ void cp_async16_cg(unsigned int saddr, const float* g, int src_bytes) {
    asm volatile("cp.async.cg.shared.global [%0], [%1], 16, %2;\n"
                 :: "r"(saddr), "l"(g), "r"(src_bytes) : "memory");
}

__global__ __launch_bounds__(THREADS) void lowpass_fir_kernel(
    const float* __restrict__ clip,
    float* __restrict__ out,
    FirParams p)
{
    __shared__ alignas(16) float buf[WARPS][STAGES][WBUF_F];

    const int tid  = threadIdx.x;
    const int warp = tid >> 5;
    const int lane = tid & 31;

    const size_t row = (size_t)blockIdx.y * T_LEN;
    const float* __restrict__ x = clip + row;
    float* __restrict__ o = out + row;

    const int strip0 = blockIdx.x * SPB + warp * WSPAN;

    const unsigned int sb0 =
        (unsigned int)__cvta_generic_to_shared(&buf[warp][0][0]);

    // Issue this warp's async copy of tile `ti` into its stage (ti % STAGES).
    auto issue_tile = [&](int ti) {
        const int g = strip0 + ti * WTILE;
        const unsigned int sbase = sb0 + (unsigned int)((ti & (STAGES - 1)) * (WBUF_F * 4));
        // 36 float4: lanes 0-31 take v = lane; lanes 0-3 also take v = 32+lane.
        {
            const int base = g - WHALO + 4 * lane;
            const bool valid = (base >= 0) && (base <= T_LEN - 4);
            const float* gp = valid ? (x + base) : x;
            cp_async16_cg(sbase + 16u * (unsigned int)lane, gp, valid ? 16 : 0);
        }
        if (lane < WBUF_V4 - 32) {
            const int v = 32 + lane;
            const int base = g - WHALO + 4 * v;
            const bool valid = (base >= 0) && (base <= T_LEN - 4);
            const float* gp = valid ? (x + base) : x;
            cp_async16_cg(sbase + 16u * (unsigned int)v, gp, valid ? 16 : 0);
        }
        asm volatile("cp.async.commit_group;\n" ::: "memory");
    };

    // Prologue: fill 3 of 4 stages.
    issue_tile(0);
    issue_tile(1);
    issue_tile(2);

    for (int i = 0; i < NTW; i++) {
        if (i + 3 < NTW) {
            asm volatile("cp.async.wait_group 2;\n" ::: "memory");  // tile i done
        } else {
            asm volatile("cp.async.wait_group 0;\n" ::: "memory");  // tail drain
        }
        __syncwarp();                       // cross-lane visibility within warp

        if (i + 3 < NTW) issue_tile(i + 3); // stage (i+3)&3 == (i-1)&3, already consumed

        const int g = strip0 + i * WTILE;
        const float* __restrict__ sm = &buf[warp][i & (STAGES - 1)][0];

        const int ofs = lane * 4;           // 4 outputs per lane
        const int t = g + ofs;
        if (t < T_LEN) {
            // Window w[j] = x[t - 12 + j] = sm[ofs + 4 + j], j = 0..15.
            // 16B lane stride -> conflict-free LDS.128.
            const float4* __restrict__ w4 =
                reinterpret_cast<const float4*>(sm + ofs + 4);
            float w[16];
            #pragma unroll
            for (int j = 0; j < 4; j++) {
                float4 v = w4[j];
                w[4 * j + 0] = v.x;
                w[4 * j + 1] = v.y;
                w[4 * j + 2] = v.z;
                w[4 * j + 3] = v.w;
            }

            float y0 = 0.f, y1 = 0.f, y2 = 0.f, y3 = 0.f;
            #pragma unroll
            for (int k = 0; k < K_TAPS; k++) {
                const float hk = p.h[k];
                y0 = fmaf(hk, w[12 + 0 - k], y0);
                y1 = fmaf(hk, w[12 + 1 - k], y1);
                y2 = fmaf(hk, w[12 + 2 - k], y2);
                y3 = fmaf(hk, w[12 + 3 - k], y3);
            }

            float4 r;
            r.x = y0; r.y = y1; r.z = y2; r.w = y3;
            *reinterpret_cast<float4*>(o + t) = r;   // coalesced store
        }
        __syncwarp();   // all lanes done reading stage (i&3) before next refill
    }
}

extern "C" void kernel_launch(void* const* d_in, const int* in_sizes, int n_in,
                              void* d_out, int out_size)
{
    const float* clip = (const float*)d_in[0];
    float* out = (float*)d_out;

    const int total = in_sizes[0];
    const int batch = total / T_LEN;   // 128

    // Coefficients in double, exactly as the reference computes them.
    const double fs = 44100.0, fc = 10000.0, q = 0.707;
    const double w0 = 2.0 * M_PI * fc / fs;
    const double alpha = sin(w0) / (2.0 * q);
    const double cw = cos(w0);
    const double a0 = 1.0 + alpha;
    const double b0 = ((1.0 - cw) / 2.0) / a0;
    const double b1 = (1.0 - cw) / a0;
    const double b2 = b0;
    const double a1 = (-2.0 * cw) / a0;
    const double a2 = (1.0 - alpha) / a0;

    // Impulse response of the biquad (truncated to K_TAPS).
    double hd[K_TAPS];
    hd[0] = b0;
    hd[1] = b1 - a1 * hd[0];
    hd[2] = b2 - a1 * hd[1] - a2 * hd[0];
    for (int k = 3; k < K_TAPS; k++)
        hd[k] = -a1 * hd[k - 1] - a2 * hd[k - 2];

    FirParams p;
    for (int k = 0; k < K_TAPS; k++) p.h[k] = (float)hd[k];

    dim3 grid(BLOCKS_X, batch);   // 9 x 128 = 1152 blocks, one wave @ 8/SM
    lowpass_fir_kernel<<<grid, THREADS>>>(clip, out, p);
}